// round 16
// baseline (speedup 1.0000x reference)
#include <cuda_runtime.h>
#include <cuda_bf16.h>
#include <cstdint>

// ---------------------------------------------------------------------------
// Problem constants
// ---------------------------------------------------------------------------
#define BDIM 256      // batch rows
#define EDIM 4096     // codes
#define KDIM 16384    // embedding dim

// GEMM tiling
#define BM 128        // batch rows per CTA
#define BN 64         // codes per CTA
#define BK 128        // k per stage = 2 SW128 sub-tiles of 64 bf16
#define NCHUNK (KDIM / BK)                    // 128
#define SUB_A_BYTES (BM * 64 * 2)             // 16384
#define SUB_B_BYTES (BN * 64 * 2)             // 8192
#define SUB_BYTES (SUB_A_BYTES + SUB_B_BYTES) // 24576
#define STAGE_BYTES (2 * SUB_BYTES)           // 49152
#define NSTAGE 4
#define DYN_SMEM (NSTAGE * STAGE_BYTES + 128) // 196736
#define NTILE (EDIM / BN)                     // 64 code tiles

#define MARGIN 12.0f
#define MAXCAND 64
#define MAXWORK (BDIM * MAXCAND)

__device__ unsigned long long g_best[BDIM];
__device__ unsigned long long g_rowbest[BDIM];            // exact-rescore results
__device__ unsigned long long g_tilemin[BDIM * NTILE];    // per-(row,tile) packed min
__device__ int g_nwork;
__device__ unsigned int g_work[MAXWORK];                  // packed (b<<12)|e
__device__ float g_keys[BDIM * EDIM];                     // approx keys (4 MB)
__device__ float g_esq[EDIM];                             // exact ||e||^2
__device__ __nv_bfloat16 g_wb[(size_t)EDIM * KDIM];       // bf16 codebook (128 MB)
__device__ __nv_bfloat16 g_ab[(size_t)BDIM * KDIM];       // bf16 inputs (8 MB)

// ---------------------------------------------------------------------------
// Helpers
// ---------------------------------------------------------------------------
__device__ __forceinline__ uint32_t smem_u32(const void* p) {
    uint32_t a;
    asm("{ .reg .u64 t; cvta.to.shared.u64 t, %1; cvt.u32.u64 %0, t; }" : "=r"(a) : "l"(p));
    return a;
}

#define SW128(o) ((o) ^ (((o) >> 3) & 0x70))

__device__ __forceinline__ unsigned int ordered_float(float f) {
    unsigned int u = __float_as_uint(f);
    return (u & 0x80000000u) ? ~u : (u | 0x80000000u);
}
__device__ __forceinline__ float inv_ordered(unsigned int o) {
    unsigned int u = (o & 0x80000000u) ? (o ^ 0x80000000u) : ~o;
    return __uint_as_float(u);
}

// pack two fp32 -> bf16x2 (lo in low half)
__device__ __forceinline__ uint32_t pk_bf2(float lo, float hi) {
    uint32_t r;
    asm("cvt.rn.bf16x2.f32 %0, %1, %2;" : "=r"(r) : "f"(hi), "f"(lo));
    return r;
}

__device__ __forceinline__ void ldsm4(uint32_t* r, uint32_t addr) {
    asm volatile("ldmatrix.sync.aligned.m8n8.x4.shared.b16 {%0,%1,%2,%3}, [%4];"
                 : "=r"(r[0]), "=r"(r[1]), "=r"(r[2]), "=r"(r[3]) : "r"(addr));
}

__device__ __forceinline__ void mma16816(float* d, const uint32_t* a,
                                         uint32_t b0, uint32_t b1) {
    asm volatile("mma.sync.aligned.m16n8k16.row.col.f32.bf16.bf16.f32 "
                 "{%0,%1,%2,%3}, {%4,%5,%6,%7}, {%8,%9}, {%0,%1,%2,%3};"
                 : "+f"(d[0]), "+f"(d[1]), "+f"(d[2]), "+f"(d[3])
                 : "r"(a[0]), "r"(a[1]), "r"(a[2]), "r"(a[3]), "r"(b0), "r"(b1));
}

__device__ __forceinline__ void cp_async16(uint32_t dst, const void* src) {
    asm volatile("cp.async.cg.shared.global [%0], [%1], 16;"
                 :: "r"(dst), "l"(src) : "memory");
}
#define CP_COMMIT() asm volatile("cp.async.commit_group;" ::: "memory")
#define CP_WAIT2()  asm volatile("cp.async.wait_group 2;" ::: "memory")

// ---------------------------------------------------------------------------
// Kernel 1: fp32 -> bf16 conversion pass + exact ||e||^2 per code.
// One warp per FULL row (128 iters x 32 lanes x 4 floats = 16384 = KDIM).
// Streaming loads (__ldcs): fp32 sources are never re-read here — keep L2
// clean for the GEMM's bf16 working set. Block 0 also resets the small
// bookkeeping state (same-kernel completion ordering suffices).
// ---------------------------------------------------------------------------
__global__ __launch_bounds__(256)
void vq_convert_kernel(const float* __restrict__ A, const float* __restrict__ W) {
    const int t    = threadIdx.x;
    const int gw   = blockIdx.x * 8 + (t >> 5);
    const int lane = t & 31;

    if (blockIdx.x == 0) {
        if (t < BDIM) {
            g_best[t]    = 0xFFFFFFFFFFFFFFFFULL;
            g_rowbest[t] = 0xFFFFFFFFFFFFFFFFULL;
        }
        if (t == 0) g_nwork = 0;
    }

    if (gw < EDIM) {
        const float4* src = (const float4*)(W + (size_t)gw * KDIM);
        __nv_bfloat16* dst = g_wb + (size_t)gw * KDIM;
        float esq = 0.0f;
#pragma unroll 16
        for (int k = 0; k < KDIM / 128; k++) {
            float4 v = __ldcs(src + lane + 32 * k);
            esq += v.x * v.x + v.y * v.y + v.z * v.z + v.w * v.w;
            uint2 p = make_uint2(pk_bf2(v.x, v.y), pk_bf2(v.z, v.w));
            *(uint2*)(dst + (size_t)(lane + 32 * k) * 4) = p;
        }
#pragma unroll
        for (int o = 16; o; o >>= 1) esq += __shfl_xor_sync(0xffffffffu, esq, o);
        if (lane == 0) g_esq[gw] = esq;
    } else if (gw < EDIM + BDIM) {
        const int r = gw - EDIM;
        const float4* src = (const float4*)(A + (size_t)r * KDIM);
        __nv_bfloat16* dst = g_ab + (size_t)r * KDIM;
#pragma unroll 16
        for (int k = 0; k < KDIM / 128; k++) {
            float4 v = __ldcs(src + lane + 32 * k);
            uint2 p = make_uint2(pk_bf2(v.x, v.y), pk_bf2(v.z, v.w));
            *(uint2*)(dst + (size_t)(lane + 32 * k) * 4) = p;
        }
    }
}

// ---------------------------------------------------------------------------
// Kernel 2: bf16 mma.sync GEMM (f32 accumulate), cp.async 4-stage, BK=128
// (2 SW128 sub-tiles per stage)
// grid (EDIM/BN, BDIM/BM) = (64, 2); 256 threads (8 warps, 32x32 each)
// ---------------------------------------------------------------------------
__global__ __launch_bounds__(256, 1)
void vq_main_kernel() {
    extern __shared__ char dynraw[];
    __shared__ float esq_sh[BN];
    __shared__ unsigned long long best_sh[BM];

    const int t    = threadIdx.x;
    const int lane = t & 31;
    const int wid  = t >> 5;
    const int bn0  = blockIdx.x * BN;
    const int bm0  = blockIdx.y * BM;
    const int wm   = (wid & 3) * 32;
    const int wn   = (wid >> 2) * 32;

    const uint32_t sbase = (smem_u32(dynraw) + 127u) & ~127u;

    if (t < BM) best_sh[t] = 0xFFFFFFFFFFFFFFFFULL;
    if (t < BN) esq_sh[t] = g_esq[bn0 + t];

    float acc[2][4][4];
#pragma unroll
    for (int im = 0; im < 2; im++)
#pragma unroll
        for (int in = 0; in < 4; in++)
#pragma unroll
            for (int q = 0; q < 4; q++) acc[im][in][q] = 0.0f;

    // producer mapping: per sub-tile 1536 16B segments, 6 per thread;
    // each thread covers both sub-tiles (12 cp.async per chunk).
    uint32_t doff[6];
    const char* src[6];
#pragma unroll
    for (int k = 0; k < 6; k++) {
        const int seg = t + 256 * k;
        const int row = seg >> 3;
        const int c16 = seg & 7;
        if (row < BM) {
            doff[k] = SW128((uint32_t)(row * 128 + c16 * 16));
            src[k]  = (const char*)(g_ab + (size_t)(bm0 + row) * KDIM + c16 * 8);
        } else {
            const int r = row - BM;
            doff[k] = SUB_A_BYTES + SW128((uint32_t)(r * 128 + c16 * 16));
            src[k]  = (const char*)(g_wb + (size_t)(bn0 + r) * KDIM + c16 * 8);
        }
    }

#define ISSUE(c) do {                                                        \
        const uint32_t _st = sbase + (uint32_t)((c) % NSTAGE) * STAGE_BYTES; \
        _Pragma("unroll")                                                    \
        for (int _k = 0; _k < 6; _k++) {                                     \
            const char* _s = src[_k] + (size_t)(c) * 256;                    \
            cp_async16(_st + doff[_k], _s);                                  \
            cp_async16(_st + SUB_BYTES + doff[_k], _s + 128);                \
        }                                                                    \
    } while (0)

    ISSUE(0); CP_COMMIT();
    ISSUE(1); CP_COMMIT();
    ISSUE(2); CP_COMMIT();

    for (int c = 0; c < NCHUNK; c++) {
        CP_WAIT2();            // chunk c resident (<=2 newer groups pending)
        __syncthreads();       // all threads done computing chunk c-1
        if (c + 3 < NCHUNK) ISSUE(c + 3);   // overwrites stage (c-1)%4: safe
        CP_COMMIT();

        const uint32_t stg = sbase + (uint32_t)(c % NSTAGE) * STAGE_BYTES;

#pragma unroll
        for (int sub = 0; sub < 2; sub++) {
            const uint32_t sA = stg + (uint32_t)sub * SUB_BYTES;
            const uint32_t sB = sA + SUB_A_BYTES;

#pragma unroll
            for (int ks = 0; ks < 4; ks++) {
                uint32_t afr[2][4], bfr[2][4];
#pragma unroll
                for (int im = 0; im < 2; im++) {
                    const int row = wm + im * 16 + (lane & 15);
                    uint32_t off = (uint32_t)(row * 128 + ks * 32 + (lane >> 4) * 16);
                    ldsm4(afr[im], sA + SW128(off));
                }
#pragma unroll
                for (int j = 0; j < 2; j++) {
                    const int row = wn + 16 * j + (lane & 7) + ((lane >> 4) & 1) * 8;
                    uint32_t off = (uint32_t)(row * 128 + ks * 32 + ((lane >> 3) & 1) * 16);
                    ldsm4(bfr[j], sB + SW128(off));
                }
#pragma unroll
                for (int im = 0; im < 2; im++)
#pragma unroll
                    for (int in = 0; in < 4; in++)
                        mma16816(acc[im][in], afr[im],
                                 bfr[in >> 1][(in & 1) * 2],
                                 bfr[in >> 1][(in & 1) * 2 + 1]);
            }
        }
    }
#undef ISSUE

    __syncthreads();

    // ---- epilogue: approx keys + per-row packed argmin ----
#pragma unroll
    for (int im = 0; im < 2; im++) {
#pragma unroll
        for (int qh = 0; qh < 2; qh++) {
            const int m = wm + im * 16 + qh * 8 + (lane >> 2);
            unsigned long long best = 0xFFFFFFFFFFFFFFFFULL;
            float* krow = g_keys + (size_t)(bm0 + m) * EDIM + bn0;
#pragma unroll
            for (int in = 0; in < 4; in++) {
                const int n = wn + in * 8 + (lane & 3) * 2;
                float k0 = esq_sh[n]     - 2.0f * acc[im][in][qh * 2 + 0];
                float k1 = esq_sh[n + 1] - 2.0f * acc[im][in][qh * 2 + 1];
                *(float2*)(krow + n) = make_float2(k0, k1);
                unsigned long long p0 =
                    ((unsigned long long)ordered_float(k0) << 32) | (unsigned)(bn0 + n);
                unsigned long long p1 =
                    ((unsigned long long)ordered_float(k1) << 32) | (unsigned)(bn0 + n + 1);
                best = p0 < best ? p0 : best;
                best = p1 < best ? p1 : best;
            }
            atomicMin(&best_sh[m], best);
        }
    }
    __syncthreads();
    if (t < BM) {
        unsigned long long v = best_sh[t];
        g_tilemin[(size_t)(bm0 + t) * NTILE + blockIdx.x] = v;  // per-tile min
        atomicMin(&g_best[bm0 + t], v);                         // global min
    }
}

// ---------------------------------------------------------------------------
// Kernel 3: candidate collection — one BLOCK per row (tile-min filtered).
// Zeroes the output row, then: ncand<=1 => approx argmin provably exact
// (margin >> 2x bf16 key-error) => direct write; ncand>1 => push work items.
// ---------------------------------------------------------------------------
__global__ __launch_bounds__(256)
void vq_collect_kernel(float* __restrict__ out) {
    __shared__ int ncand;
    __shared__ int cand[MAXCAND];
    __shared__ int wbase;

    const int b = blockIdx.x;
    const int t = threadIdx.x;
    if (t == 0) ncand = 0;

    // zero this row of the one-hot output (poisoned before timing)
    float4* row4 = (float4*)(out + (size_t)b * EDIM);
#pragma unroll
    for (int i = 0; i < 4; i++) row4[t + 256 * i] = make_float4(0.f, 0.f, 0.f, 0.f);
    __syncthreads();

    const unsigned long long packed = g_best[b];
    const float thr = inv_ordered((unsigned int)(packed >> 32)) + MARGIN;
    const int approx_idx = (int)(packed & 0xFFFFFFFFu);

    // tile filter: thread i (i<64) owns code tile i
    if (t < NTILE) {
        unsigned long long tm = g_tilemin[(size_t)b * NTILE + t];
        float tkey = inv_ordered((unsigned int)(tm >> 32));
        if (tkey <= thr) {
            const float4* kp = (const float4*)(g_keys + (size_t)b * EDIM + t * BN);
#pragma unroll 4
            for (int i = 0; i < BN / 4; i++) {
                float4 kv = kp[i];
                int base = t * BN + i * 4;
                if (kv.x <= thr) { int j = atomicAdd(&ncand, 1); if (j < MAXCAND) cand[j] = base; }
                if (kv.y <= thr) { int j = atomicAdd(&ncand, 1); if (j < MAXCAND) cand[j] = base + 1; }
                if (kv.z <= thr) { int j = atomicAdd(&ncand, 1); if (j < MAXCAND) cand[j] = base + 2; }
                if (kv.w <= thr) { int j = atomicAdd(&ncand, 1); if (j < MAXCAND) cand[j] = base + 3; }
            }
        }
    }
    __syncthreads();

    if (ncand <= 1) {
        if (t == 0) out[(size_t)b * EDIM + approx_idx] = 1.0f;
        return;
    }

    const int nc = ncand < MAXCAND ? ncand : MAXCAND;
    if (t == 0) wbase = atomicAdd(&g_nwork, nc);
    __syncthreads();
    if (t < nc) g_work[wbase + t] = ((unsigned)b << 12) | (unsigned)cand[t];
}

// ---------------------------------------------------------------------------
// Kernel 4: exact fp32 rescore — one BLOCK per work item (grid-stride).
// ---------------------------------------------------------------------------
__global__ __launch_bounds__(256)
void vq_exact_kernel(const float* __restrict__ A, const float* __restrict__ W) {
    __shared__ float warp_red[8];
    const int t = threadIdx.x;
    const int nwork = g_nwork;

    for (int i = blockIdx.x; i < nwork; i += gridDim.x) {
        const unsigned w = g_work[i];
        const int b = (int)(w >> 12);
        const int e = (int)(w & 4095u);

        const float4* x4 = (const float4*)(A + (size_t)b * KDIM);
        const float4* w4 = (const float4*)(W + (size_t)e * KDIM);
        float acc = 0.0f;
#pragma unroll 4
        for (int q = 0; q < 16; q++) {
            float4 wv = w4[t + q * 256];
            float4 xv = x4[t + q * 256];
            acc += wv.x * (wv.x - 2.0f * xv.x) + wv.y * (wv.y - 2.0f * xv.y)
                 + wv.z * (wv.z - 2.0f * xv.z) + wv.w * (wv.w - 2.0f * xv.w);
        }
#pragma unroll
        for (int o = 16; o > 0; o >>= 1) acc += __shfl_xor_sync(0xffffffffu, acc, o);
        if ((t & 31) == 0) warp_red[t >> 5] = acc;
        __syncthreads();
        if (t == 0) {
            float tot = 0.0f;
#pragma unroll
            for (int v = 0; v < 8; v++) tot += warp_red[v];
            unsigned long long p =
                ((unsigned long long)ordered_float(tot) << 32) | (unsigned int)e;
            atomicMin(&g_rowbest[b], p);
        }
        __syncthreads();
    }
}

// ---------------------------------------------------------------------------
// Kernel 5: writeout for multi-candidate rows (rows already zeroed)
// ---------------------------------------------------------------------------
__global__ void vq_write_kernel(float* __restrict__ out) {
    const int b = threadIdx.x;
    if (b < BDIM) {
        unsigned long long p = g_rowbest[b];
        if (p != 0xFFFFFFFFFFFFFFFFULL)
            out[(size_t)b * EDIM + (unsigned int)(p & 0xFFFFFFFFu)] = 1.0f;
    }
}

// ---------------------------------------------------------------------------
// Host launch
// ---------------------------------------------------------------------------
extern "C" void kernel_launch(void* const* d_in, const int* in_sizes, int n_in,
                              void* d_out, int out_size) {
    const float* inputs = (const float*)d_in[0];   // [256, 16384]
    const float* codes  = (const float*)d_in[1];   // [4096, 16384]
    float* out = (float*)d_out;                    // [256, 4096]

    cudaFuncSetAttribute(vq_main_kernel,
                         cudaFuncAttributeMaxDynamicSharedMemorySize, DYN_SMEM);

    vq_convert_kernel<<<(EDIM + BDIM) / 8, 256>>>(inputs, codes);

    dim3 grid(EDIM / BN, BDIM / BM);   // (64, 2)
    vq_main_kernel<<<grid, 256, DYN_SMEM>>>();

    vq_collect_kernel<<<BDIM, 256>>>(out);
    vq_exact_kernel<<<256, 256>>>(inputs, codes);
    vq_write_kernel<<<1, 256>>>(out);
}

// round 17
// speedup vs baseline: 1.1145x; 1.1145x over previous
#include <cuda_runtime.h>
#include <cuda_bf16.h>
#include <cstdint>

// ---------------------------------------------------------------------------
// Problem constants
// ---------------------------------------------------------------------------
#define BDIM 256      // batch rows
#define EDIM 4096     // codes
#define KDIM 16384    // embedding dim

// GEMM tiling
#define BM 128        // batch rows per CTA
#define BN 64         // codes per CTA
#define BK 128        // k per stage = 2 SW128 sub-tiles of 64 bf16
#define NCHUNK (KDIM / BK)                    // 128
#define SUB_A_BYTES (BM * 64 * 2)             // 16384
#define SUB_B_BYTES (BN * 64 * 2)             // 8192
#define SUB_BYTES (SUB_A_BYTES + SUB_B_BYTES) // 24576
#define STAGE_BYTES (2 * SUB_BYTES)           // 49152
#define NSTAGE 4
#define DYN_SMEM (NSTAGE * STAGE_BYTES + 128) // 196736
#define NTILE (EDIM / BN)                     // 64 code tiles

#define MARGIN 12.0f
#define MAXCAND 64
#define MAXWORK (BDIM * MAXCAND)

__device__ unsigned long long g_best[BDIM];
__device__ unsigned long long g_rowbest[BDIM];            // exact-rescore results
__device__ unsigned long long g_tilemin[BDIM * NTILE];    // per-(row,tile) packed min
__device__ int g_nwork;
__device__ unsigned int g_work[MAXWORK];                  // packed (b<<12)|e
__device__ float g_keys[BDIM * EDIM];                     // approx keys (4 MB)
__device__ float g_esq[EDIM];                             // exact ||e||^2
__device__ __nv_bfloat16 g_wb[(size_t)EDIM * KDIM];       // bf16 codebook (128 MB)
__device__ __nv_bfloat16 g_ab[(size_t)BDIM * KDIM];       // bf16 inputs (8 MB)

// ---------------------------------------------------------------------------
// Helpers
// ---------------------------------------------------------------------------
__device__ __forceinline__ uint32_t smem_u32(const void* p) {
    uint32_t a;
    asm("{ .reg .u64 t; cvta.to.shared.u64 t, %1; cvt.u32.u64 %0, t; }" : "=r"(a) : "l"(p));
    return a;
}

#define SW128(o) ((o) ^ (((o) >> 3) & 0x70))

__device__ __forceinline__ unsigned int ordered_float(float f) {
    unsigned int u = __float_as_uint(f);
    return (u & 0x80000000u) ? ~u : (u | 0x80000000u);
}
__device__ __forceinline__ float inv_ordered(unsigned int o) {
    unsigned int u = (o & 0x80000000u) ? (o ^ 0x80000000u) : ~o;
    return __uint_as_float(u);
}

// pack two fp32 -> bf16x2 (lo in low half)
__device__ __forceinline__ uint32_t pk_bf2(float lo, float hi) {
    uint32_t r;
    asm("cvt.rn.bf16x2.f32 %0, %1, %2;" : "=r"(r) : "f"(hi), "f"(lo));
    return r;
}

__device__ __forceinline__ void ldsm4(uint32_t* r, uint32_t addr) {
    asm volatile("ldmatrix.sync.aligned.m8n8.x4.shared.b16 {%0,%1,%2,%3}, [%4];"
                 : "=r"(r[0]), "=r"(r[1]), "=r"(r[2]), "=r"(r[3]) : "r"(addr));
}

__device__ __forceinline__ void mma16816(float* d, const uint32_t* a,
                                         uint32_t b0, uint32_t b1) {
    asm volatile("mma.sync.aligned.m16n8k16.row.col.f32.bf16.bf16.f32 "
                 "{%0,%1,%2,%3}, {%4,%5,%6,%7}, {%8,%9}, {%0,%1,%2,%3};"
                 : "+f"(d[0]), "+f"(d[1]), "+f"(d[2]), "+f"(d[3])
                 : "r"(a[0]), "r"(a[1]), "r"(a[2]), "r"(a[3]), "r"(b0), "r"(b1));
}

__device__ __forceinline__ void cp_async16(uint32_t dst, const void* src) {
    asm volatile("cp.async.cg.shared.global [%0], [%1], 16;"
                 :: "r"(dst), "l"(src) : "memory");
}
#define CP_COMMIT() asm volatile("cp.async.commit_group;" ::: "memory")
#define CP_WAIT2()  asm volatile("cp.async.wait_group 2;" ::: "memory")

// ---------------------------------------------------------------------------
// Kernel 1: fp32 -> bf16 conversion pass + exact ||e||^2 per code.
// One warp per FULL row (128 iters x 32 lanes x 4 floats = 16384 = KDIM).
// Block 0 additionally resets the small bookkeeping state (the consumers of
// that state launch after this kernel completes, so ordering is guaranteed).
// ---------------------------------------------------------------------------
__global__ __launch_bounds__(256)
void vq_convert_kernel(const float* __restrict__ A, const float* __restrict__ W) {
    const int t    = threadIdx.x;
    const int gw   = blockIdx.x * 8 + (t >> 5);
    const int lane = t & 31;

    if (blockIdx.x == 0) {
        if (t < BDIM) {
            g_best[t]    = 0xFFFFFFFFFFFFFFFFULL;
            g_rowbest[t] = 0xFFFFFFFFFFFFFFFFULL;
        }
        if (t == 0) g_nwork = 0;
    }

    if (gw < EDIM) {
        const float4* src = (const float4*)(W + (size_t)gw * KDIM);
        __nv_bfloat16* dst = g_wb + (size_t)gw * KDIM;
        float esq = 0.0f;
#pragma unroll 8
        for (int k = 0; k < KDIM / 128; k++) {
            float4 v = src[lane + 32 * k];
            esq += v.x * v.x + v.y * v.y + v.z * v.z + v.w * v.w;
            uint2 p = make_uint2(pk_bf2(v.x, v.y), pk_bf2(v.z, v.w));
            *(uint2*)(dst + (size_t)(lane + 32 * k) * 4) = p;
        }
#pragma unroll
        for (int o = 16; o; o >>= 1) esq += __shfl_xor_sync(0xffffffffu, esq, o);
        if (lane == 0) g_esq[gw] = esq;
    } else if (gw < EDIM + BDIM) {
        const int r = gw - EDIM;
        const float4* src = (const float4*)(A + (size_t)r * KDIM);
        __nv_bfloat16* dst = g_ab + (size_t)r * KDIM;
#pragma unroll 8
        for (int k = 0; k < KDIM / 128; k++) {
            float4 v = src[lane + 32 * k];
            uint2 p = make_uint2(pk_bf2(v.x, v.y), pk_bf2(v.z, v.w));
            *(uint2*)(dst + (size_t)(lane + 32 * k) * 4) = p;
        }
    }
}

// ---------------------------------------------------------------------------
// Kernel 2: bf16 mma.sync GEMM (f32 accumulate), cp.async 4-stage, BK=128
// (2 SW128 sub-tiles per stage)
// grid (EDIM/BN, BDIM/BM) = (64, 2); 256 threads (8 warps, 32x32 each)
// ---------------------------------------------------------------------------
__global__ __launch_bounds__(256, 1)
void vq_main_kernel() {
    extern __shared__ char dynraw[];
    __shared__ float esq_sh[BN];
    __shared__ unsigned long long best_sh[BM];

    const int t    = threadIdx.x;
    const int lane = t & 31;
    const int wid  = t >> 5;
    const int bn0  = blockIdx.x * BN;
    const int bm0  = blockIdx.y * BM;
    const int wm   = (wid & 3) * 32;
    const int wn   = (wid >> 2) * 32;

    const uint32_t sbase = (smem_u32(dynraw) + 127u) & ~127u;

    if (t < BM) best_sh[t] = 0xFFFFFFFFFFFFFFFFULL;
    if (t < BN) esq_sh[t] = g_esq[bn0 + t];

    float acc[2][4][4];
#pragma unroll
    for (int im = 0; im < 2; im++)
#pragma unroll
        for (int in = 0; in < 4; in++)
#pragma unroll
            for (int q = 0; q < 4; q++) acc[im][in][q] = 0.0f;

    // producer mapping: per sub-tile 1536 16B segments, 6 per thread;
    // each thread covers both sub-tiles (12 cp.async per chunk).
    uint32_t doff[6];
    const char* src[6];
#pragma unroll
    for (int k = 0; k < 6; k++) {
        const int seg = t + 256 * k;
        const int row = seg >> 3;
        const int c16 = seg & 7;
        if (row < BM) {
            doff[k] = SW128((uint32_t)(row * 128 + c16 * 16));
            src[k]  = (const char*)(g_ab + (size_t)(bm0 + row) * KDIM + c16 * 8);
        } else {
            const int r = row - BM;
            doff[k] = SUB_A_BYTES + SW128((uint32_t)(r * 128 + c16 * 16));
            src[k]  = (const char*)(g_wb + (size_t)(bn0 + r) * KDIM + c16 * 8);
        }
    }

#define ISSUE(c) do {                                                        \
        const uint32_t _st = sbase + (uint32_t)((c) % NSTAGE) * STAGE_BYTES; \
        _Pragma("unroll")                                                    \
        for (int _k = 0; _k < 6; _k++) {                                     \
            const char* _s = src[_k] + (size_t)(c) * 256;                    \
            cp_async16(_st + doff[_k], _s);                                  \
            cp_async16(_st + SUB_BYTES + doff[_k], _s + 128);                \
        }                                                                    \
    } while (0)

    ISSUE(0); CP_COMMIT();
    ISSUE(1); CP_COMMIT();
    ISSUE(2); CP_COMMIT();

    for (int c = 0; c < NCHUNK; c++) {
        CP_WAIT2();            // chunk c resident (<=2 newer groups pending)
        __syncthreads();       // all threads done computing chunk c-1
        if (c + 3 < NCHUNK) ISSUE(c + 3);   // overwrites stage (c-1)%4: safe
        CP_COMMIT();

        const uint32_t stg = sbase + (uint32_t)(c % NSTAGE) * STAGE_BYTES;

#pragma unroll
        for (int sub = 0; sub < 2; sub++) {
            const uint32_t sA = stg + (uint32_t)sub * SUB_BYTES;
            const uint32_t sB = sA + SUB_A_BYTES;

#pragma unroll
            for (int ks = 0; ks < 4; ks++) {
                uint32_t afr[2][4], bfr[2][4];
#pragma unroll
                for (int im = 0; im < 2; im++) {
                    const int row = wm + im * 16 + (lane & 15);
                    uint32_t off = (uint32_t)(row * 128 + ks * 32 + (lane >> 4) * 16);
                    ldsm4(afr[im], sA + SW128(off));
                }
#pragma unroll
                for (int j = 0; j < 2; j++) {
                    const int row = wn + 16 * j + (lane & 7) + ((lane >> 4) & 1) * 8;
                    uint32_t off = (uint32_t)(row * 128 + ks * 32 + ((lane >> 3) & 1) * 16);
                    ldsm4(bfr[j], sB + SW128(off));
                }
#pragma unroll
                for (int im = 0; im < 2; im++)
#pragma unroll
                    for (int in = 0; in < 4; in++)
                        mma16816(acc[im][in], afr[im],
                                 bfr[in >> 1][(in & 1) * 2],
                                 bfr[in >> 1][(in & 1) * 2 + 1]);
            }
        }
    }
#undef ISSUE

    __syncthreads();

    // ---- epilogue: approx keys + per-row packed argmin ----
#pragma unroll
    for (int im = 0; im < 2; im++) {
#pragma unroll
        for (int qh = 0; qh < 2; qh++) {
            const int m = wm + im * 16 + qh * 8 + (lane >> 2);
            unsigned long long best = 0xFFFFFFFFFFFFFFFFULL;
            float* krow = g_keys + (size_t)(bm0 + m) * EDIM + bn0;
#pragma unroll
            for (int in = 0; in < 4; in++) {
                const int n = wn + in * 8 + (lane & 3) * 2;
                float k0 = esq_sh[n]     - 2.0f * acc[im][in][qh * 2 + 0];
                float k1 = esq_sh[n + 1] - 2.0f * acc[im][in][qh * 2 + 1];
                *(float2*)(krow + n) = make_float2(k0, k1);
                unsigned long long p0 =
                    ((unsigned long long)ordered_float(k0) << 32) | (unsigned)(bn0 + n);
                unsigned long long p1 =
                    ((unsigned long long)ordered_float(k1) << 32) | (unsigned)(bn0 + n + 1);
                best = p0 < best ? p0 : best;
                best = p1 < best ? p1 : best;
            }
            atomicMin(&best_sh[m], best);
        }
    }
    __syncthreads();
    if (t < BM) {
        unsigned long long v = best_sh[t];
        g_tilemin[(size_t)(bm0 + t) * NTILE + blockIdx.x] = v;  // per-tile min
        atomicMin(&g_best[bm0 + t], v);                         // global min
    }
}

// ---------------------------------------------------------------------------
// Kernel 3: candidate collection — one BLOCK per row (tile-min filtered).
// Zeroes the output row, then: ncand<=1 => approx argmin provably exact
// (margin >> 2x bf16 key-error) => direct write; ncand>1 => push work items.
// ---------------------------------------------------------------------------
__global__ __launch_bounds__(256)
void vq_collect_kernel(float* __restrict__ out) {
    __shared__ int ncand;
    __shared__ int cand[MAXCAND];
    __shared__ int wbase;

    const int b = blockIdx.x;
    const int t = threadIdx.x;
    if (t == 0) ncand = 0;

    // zero this row of the one-hot output (poisoned before timing)
    float4* row4 = (float4*)(out + (size_t)b * EDIM);
#pragma unroll
    for (int i = 0; i < 4; i++) row4[t + 256 * i] = make_float4(0.f, 0.f, 0.f, 0.f);
    __syncthreads();

    const unsigned long long packed = g_best[b];
    const float thr = inv_ordered((unsigned int)(packed >> 32)) + MARGIN;
    const int approx_idx = (int)(packed & 0xFFFFFFFFu);

    // tile filter: thread i (i<64) owns code tile i
    if (t < NTILE) {
        unsigned long long tm = g_tilemin[(size_t)b * NTILE + t];
        float tkey = inv_ordered((unsigned int)(tm >> 32));
        if (tkey <= thr) {
            const float4* kp = (const float4*)(g_keys + (size_t)b * EDIM + t * BN);
#pragma unroll 4
            for (int i = 0; i < BN / 4; i++) {
                float4 kv = kp[i];
                int base = t * BN + i * 4;
                if (kv.x <= thr) { int j = atomicAdd(&ncand, 1); if (j < MAXCAND) cand[j] = base; }
                if (kv.y <= thr) { int j = atomicAdd(&ncand, 1); if (j < MAXCAND) cand[j] = base + 1; }
                if (kv.z <= thr) { int j = atomicAdd(&ncand, 1); if (j < MAXCAND) cand[j] = base + 2; }
                if (kv.w <= thr) { int j = atomicAdd(&ncand, 1); if (j < MAXCAND) cand[j] = base + 3; }
            }
        }
    }
    __syncthreads();

    if (ncand <= 1) {
        if (t == 0) out[(size_t)b * EDIM + approx_idx] = 1.0f;
        return;
    }

    const int nc = ncand < MAXCAND ? ncand : MAXCAND;
    if (t == 0) wbase = atomicAdd(&g_nwork, nc);
    __syncthreads();
    if (t < nc) g_work[wbase + t] = ((unsigned)b << 12) | (unsigned)cand[t];
}

// ---------------------------------------------------------------------------
// Kernel 4: exact fp32 rescore — one BLOCK per work item (grid-stride).
// ---------------------------------------------------------------------------
__global__ __launch_bounds__(256)
void vq_exact_kernel(const float* __restrict__ A, const float* __restrict__ W) {
    __shared__ float warp_red[8];
    const int t = threadIdx.x;
    const int nwork = g_nwork;

    for (int i = blockIdx.x; i < nwork; i += gridDim.x) {
        const unsigned w = g_work[i];
        const int b = (int)(w >> 12);
        const int e = (int)(w & 4095u);

        const float4* x4 = (const float4*)(A + (size_t)b * KDIM);
        const float4* w4 = (const float4*)(W + (size_t)e * KDIM);
        float acc = 0.0f;
#pragma unroll 4
        for (int q = 0; q < 16; q++) {
            float4 wv = w4[t + q * 256];
            float4 xv = x4[t + q * 256];
            acc += wv.x * (wv.x - 2.0f * xv.x) + wv.y * (wv.y - 2.0f * xv.y)
                 + wv.z * (wv.z - 2.0f * xv.z) + wv.w * (wv.w - 2.0f * xv.w);
        }
#pragma unroll
        for (int o = 16; o > 0; o >>= 1) acc += __shfl_xor_sync(0xffffffffu, acc, o);
        if ((t & 31) == 0) warp_red[t >> 5] = acc;
        __syncthreads();
        if (t == 0) {
            float tot = 0.0f;
#pragma unroll
            for (int v = 0; v < 8; v++) tot += warp_red[v];
            unsigned long long p =
                ((unsigned long long)ordered_float(tot) << 32) | (unsigned int)e;
            atomicMin(&g_rowbest[b], p);
        }
        __syncthreads();
    }
}

// ---------------------------------------------------------------------------
// Kernel 5: writeout for multi-candidate rows (rows already zeroed)
// ---------------------------------------------------------------------------
__global__ void vq_write_kernel(float* __restrict__ out) {
    const int b = threadIdx.x;
    if (b < BDIM) {
        unsigned long long p = g_rowbest[b];
        if (p != 0xFFFFFFFFFFFFFFFFULL)
            out[(size_t)b * EDIM + (unsigned int)(p & 0xFFFFFFFFu)] = 1.0f;
    }
}

// ---------------------------------------------------------------------------
// Host launch
// ---------------------------------------------------------------------------
extern "C" void kernel_launch(void* const* d_in, const int* in_sizes, int n_in,
                              void* d_out, int out_size) {
    const float* inputs = (const float*)d_in[0];   // [256, 16384]
    const float* codes  = (const float*)d_in[1];   // [4096, 16384]
    float* out = (float*)d_out;                    // [256, 4096]

    cudaFuncSetAttribute(vq_main_kernel,
                         cudaFuncAttributeMaxDynamicSharedMemorySize, DYN_SMEM);

    vq_convert_kernel<<<(EDIM + BDIM) / 8, 256>>>(inputs, codes);

    dim3 grid(EDIM / BN, BDIM / BM);   // (64, 2)
    vq_main_kernel<<<grid, 256, DYN_SMEM>>>();

    vq_collect_kernel<<<BDIM, 256>>>(out);
    vq_exact_kernel<<<256, 256>>>(inputs, codes);
    vq_write_kernel<<<1, 256>>>(out);
}